// round 5
// baseline (speedup 1.0000x reference)
#include <cuda_runtime.h>
#include <cuda_bf16.h>

// Problem shape (fixed by reference): B=4, A=9, H=256, W=256, C=9, F=64
#define B_ 4
#define A_ 9
#define H_ 256
#define W_ 256
#define C_ 9
#define F_ 64

#define ROW4 ((W_ * C_) / 4)   // 576 float4 per (b,a,h) row of lfi

// Scratch (device globals — no allocation allowed in kernel_launch)
__device__ float g_hv[B_ * W_ * F_];       // mean over H of f_maps     [b,w,f]
__device__ float g_scale[B_ * W_ * F_];    // hv / max_w hv             [b,w,f]

// ---------------------------------------------------------------------------
// Kernel B: hv[b,w,f] = mean_h f_maps[b,h,w,f]   — float4 version.
// One block per (b,w); 256 threads = 16 f4-lanes x 16 h-groups.
// Each thread: 16 fully-unrolled LDG.128 (independent addresses -> MLP=16).
// A warp covers two full 256B (h)-rows -> perfectly coalesced.
// ---------------------------------------------------------------------------
__global__ void colmean_fmaps_kernel(const float4* __restrict__ fm4) {
    __shared__ float4 sm[256];
    int bid = blockIdx.x;                // 0 .. B*W-1
    int b = bid >> 8;
    int w = bid & (W_ - 1);
    int tid = threadIdx.x;
    int f4 = tid & 15;
    int hq = tid >> 4;                   // 0..15

    // fm4 index: ((b*H + h)*W + w)*16 + f4
    const float4* p = fm4 + ((size_t)(b * H_) * W_ + w) * 16 + f4;
    float4 s = make_float4(0.f, 0.f, 0.f, 0.f);
    int h0 = hq * 16;
#pragma unroll
    for (int i = 0; i < 16; i++) {
        float4 v = p[(size_t)(h0 + i) * (W_ * 16)];
        s.x += v.x; s.y += v.y; s.z += v.z; s.w += v.w;
    }
    sm[tid] = s;
    __syncthreads();
    // reduce over the 16 h-groups (stride-16 layout: tid = f4 + 16*hq)
#pragma unroll
    for (int off = 8; off > 0; off >>= 1) {
        if (hq < off) {
            float4 o = sm[tid + 16 * off];
            s.x += o.x; s.y += o.y; s.z += o.z; s.w += o.w;
            sm[tid] = s;
        }
        __syncthreads();
    }
    if (tid < 16) {
        float4 r = sm[tid];
        r.x *= (1.0f / H_); r.y *= (1.0f / H_);
        r.z *= (1.0f / H_); r.w *= (1.0f / H_);
        reinterpret_cast<float4*>(g_hv)[(b * W_ + w) * 16 + tid] = r;
    }
}

// ---------------------------------------------------------------------------
// Kernel C: scale[b,w,f] = hv[b,w,f] / max_w' hv[b,w',f]
// One block per (b,f); 256 threads over w. Tiny, latency-irrelevant.
// ---------------------------------------------------------------------------
__global__ void normalize_kernel() {
    __shared__ float sm[256];
    int bid = blockIdx.x;                // 0 .. B*F-1
    int b = bid >> 6;
    int f = bid & (F_ - 1);
    int w = threadIdx.x;

    float v = g_hv[(b * W_ + w) * F_ + f];
    sm[w] = v;
    __syncthreads();
#pragma unroll
    for (int off = 128; off > 0; off >>= 1) {
        if (w < off) sm[w] = fmaxf(sm[w], sm[w + off]);
        __syncthreads();
    }
    float inv = 1.0f / sm[0];
    g_scale[(b * W_ + w) * F_ + f] = v * inv;
}

// ---------------------------------------------------------------------------
// Fused A+D: one block per (b,h).
// Phase 1 (vectorized + software-pipelined): for each a, the row
// lfi[b,a,h,:,:] (9216B = 576 float4) is staged cooperatively into smem with
// LDG.128 register-prefetch of row a+1 overlapping the smem-summation of row
// a. Thread w then sums its 9 contiguous floats per row (stride-9 words,
// gcd(9,32)=1 -> conflict-free LDS).
// Phase 2: write out[b,h,:,:] (64KB) as 16 independent STG.128 per thread.
// ---------------------------------------------------------------------------
__global__ void fused_m_out_kernel(const float* __restrict__ lfi,
                                   float4* __restrict__ out) {
    __shared__ float4 buf[2][ROW4];      // 2 x 9216B double buffer
    __shared__ float sm_m[W_];           // m[b,h,w]
    __shared__ float4 sm_s[F_ / 4];      // scale[b,h,f]

    int bid = blockIdx.x;                // 0 .. B*H-1
    int b = bid >> 8;
    int h = bid & (H_ - 1);
    int tid = threadIdx.x;               // 0..255

    // stage scale row (h indexes scale's w-dimension per reference transpose)
    if (tid < F_ / 4) {
        sm_s[tid] = reinterpret_cast<const float4*>(g_scale)[(b * W_ + h) * (F_ / 4) + tid];
    }

    const float4* lfi4 = reinterpret_cast<const float4*>(lfi);
    // float4 row base for (b, a, h):  ((b*A + a)*H + h) * 576
    size_t rowbase = ((size_t)(b * A_) * H_ + h) * ROW4;
    size_t rowstep = (size_t)H_ * ROW4;  // advance one a

    // preload a=0 into registers
    float4 r0, r1, r2;
    {
        const float4* src = lfi4 + rowbase;
        r0 = src[tid];
        r1 = src[tid + 256];
        if (tid < ROW4 - 512) r2 = src[tid + 512];
    }

    float acc = 0.f;
#pragma unroll
    for (int a = 0; a < A_; a++) {
        // store current row's registers to buf[a&1]
        float4* dst = buf[a & 1];
        dst[tid] = r0;
        dst[tid + 256] = r1;
        if (tid < ROW4 - 512) dst[tid + 512] = r2;
        __syncthreads();

        // prefetch next row into registers (overlaps the summation below)
        if (a + 1 < A_) {
            const float4* src = lfi4 + rowbase + (size_t)(a + 1) * rowstep;
            r0 = src[tid];
            r1 = src[tid + 256];
            if (tid < ROW4 - 512) r2 = src[tid + 512];
        }

        // sum my 9 floats (w = tid) from the staged row
        const float* row = reinterpret_cast<const float*>(buf[a & 1]) + tid * C_;
        float t0 = row[0] + row[1] + row[2];
        float t1 = row[3] + row[4] + row[5];
        float t2 = row[6] + row[7] + row[8];
        acc += t0 + t1 + t2;
        __syncthreads();   // all reads of buf[a&1] done before next store
    }
    sm_m[tid] = acc * (1.0f / (A_ * C_));
    __syncthreads();

    // phase 2: write 4096 float4s = out[b,h,:,:]
    float4* orow = out + (size_t)(b * H_ + h) * (W_ * F_ / 4);
#pragma unroll
    for (int k = 0; k < 16; k++) {
        int idx = k * 256 + tid;         // 0..4095
        int w  = idx >> 4;
        int f4 = idx & 15;
        float mv = sm_m[w];
        float4 sc = sm_s[f4];
        float4 o;
        o.x = mv * sc.x;
        o.y = mv * sc.y;
        o.z = mv * sc.z;
        o.w = mv * sc.w;
        orow[idx] = o;
    }
}

extern "C" void kernel_launch(void* const* d_in, const int* in_sizes, int n_in,
                              void* d_out, int out_size) {
    const float* lfi = (const float*)d_in[0];          // [4,9,256,256,9]
    const float4* fm4 = (const float4*)d_in[1];        // [4,256,256,64] as float4
    float4* out = (float4*)d_out;                      // [4,256,256,64]

    colmean_fmaps_kernel<<<B_ * W_, 256>>>(fm4);       // B: block per (b,w)
    normalize_kernel<<<B_ * F_, 256>>>();              // C: block per (b,f)
    fused_m_out_kernel<<<B_ * H_, 256>>>((const float*)lfi, out); // A+D
}

// round 7
// speedup vs baseline: 1.0826x; 1.0826x over previous
#include <cuda_runtime.h>
#include <cuda_bf16.h>

// Problem shape (fixed by reference): B=4, A=9, H=256, W=256, C=9, F=64
#define B_ 4
#define A_ 9
#define H_ 256
#define W_ 256
#define C_ 9
#define F_ 64

// Scratch (device globals — no allocation allowed in kernel_launch)
__device__ float g_hv[B_ * W_ * F_];       // mean over H of f_maps     [b,w,f]
__device__ float g_scale[B_ * W_ * F_];    // hv / max_w hv             [b,w,f]

// ---------------------------------------------------------------------------
// Kernel B: hv[b,w,f] = mean_h f_maps[b,h,w,f]   — float4, evict-first loads.
// One block per (b,w); 256 threads = 16 f4-lanes x 16 h-groups.
// ---------------------------------------------------------------------------
__global__ void colmean_fmaps_kernel(const float4* __restrict__ fm4) {
    __shared__ float4 sm[256];
    int bid = blockIdx.x;                // 0 .. B*W-1
    int b = bid >> 8;
    int w = bid & (W_ - 1);
    int tid = threadIdx.x;
    int f4 = tid & 15;
    int hq = tid >> 4;                   // 0..15

    const float4* p = fm4 + ((size_t)(b * H_) * W_ + w) * 16 + f4;
    float4 s = make_float4(0.f, 0.f, 0.f, 0.f);
    int h0 = hq * 16;
#pragma unroll
    for (int i = 0; i < 16; i++) {
        float4 v = __ldcs(&p[(size_t)(h0 + i) * (W_ * 16)]);
        s.x += v.x; s.y += v.y; s.z += v.z; s.w += v.w;
    }
    sm[tid] = s;
    __syncthreads();
#pragma unroll
    for (int off = 8; off > 0; off >>= 1) {
        if (hq < off) {
            float4 o = sm[tid + 16 * off];
            s.x += o.x; s.y += o.y; s.z += o.z; s.w += o.w;
            sm[tid] = s;
        }
        __syncthreads();
    }
    if (tid < 16) {
        float4 r = sm[tid];
        r.x *= (1.0f / H_); r.y *= (1.0f / H_);
        r.z *= (1.0f / H_); r.w *= (1.0f / H_);
        reinterpret_cast<float4*>(g_hv)[(b * W_ + w) * 16 + tid] = r;
    }
}

// ---------------------------------------------------------------------------
// Kernel C: scale[b,w,f] = hv[b,w,f] / max_w' hv[b,w',f]
// One block per (b,f); 256 threads over w. Tiny, latency-irrelevant.
// ---------------------------------------------------------------------------
__global__ void normalize_kernel() {
    __shared__ float sm[256];
    int bid = blockIdx.x;                // 0 .. B*F-1
    int b = bid >> 6;
    int f = bid & (F_ - 1);
    int w = threadIdx.x;

    float v = g_hv[(b * W_ + w) * F_ + f];
    sm[w] = v;
    __syncthreads();
#pragma unroll
    for (int off = 128; off > 0; off >>= 1) {
        if (w < off) sm[w] = fmaxf(sm[w], sm[w + off]);
        __syncthreads();
    }
    float inv = 1.0f / sm[0];
    g_scale[(b * W_ + w) * F_ + f] = v * inv;
}

// ---------------------------------------------------------------------------
// Fused A+D (direct form + streaming hints): one block per (b,h).
//   Phase 1: thread tid computes m[w=tid] via 81 coalesced evict-first
//            scalar loads (warp spans 1152B contiguous per a).
//   Phase 2: write out[b,h,:,:] = 64KB as 16 independent evict-first
//            STG.128 per thread, operands from shared.
// ---------------------------------------------------------------------------
__global__ void fused_m_out_kernel(const float* __restrict__ lfi,
                                   float4* __restrict__ out) {
    __shared__ float sm_m[W_];           // m[b,h,w]
    __shared__ float4 sm_s[F_ / 4];      // scale[b,h,f]

    int bid = blockIdx.x;                // 0 .. B*H-1
    int b = bid >> 8;
    int h = bid & (H_ - 1);
    int tid = threadIdx.x;               // 0..255 == w

    // stage scale row (h indexes scale's w-dimension per reference transpose)
    if (tid < F_ / 4) {
        sm_s[tid] = reinterpret_cast<const float4*>(g_scale)[(b * W_ + h) * (F_ / 4) + tid];
    }

    // phase 1: m for w = tid
    {
        int w = tid;
        float s0 = 0.f, s1 = 0.f, s2 = 0.f;
#pragma unroll
        for (int a = 0; a < A_; a++) {
            const float* p = lfi + ((((size_t)b * A_ + a) * H_ + h) * W_ + w) * C_;
            s0 += __ldcs(p + 0) + __ldcs(p + 3) + __ldcs(p + 6);
            s1 += __ldcs(p + 1) + __ldcs(p + 4) + __ldcs(p + 7);
            s2 += __ldcs(p + 2) + __ldcs(p + 5) + __ldcs(p + 8);
        }
        sm_m[w] = (s0 + s1 + s2) * (1.0f / (A_ * C_));
    }
    __syncthreads();

    // phase 2: write 4096 float4s = out[b,h,:,:]
    float4* orow = out + (size_t)(b * H_ + h) * (W_ * F_ / 4);
#pragma unroll
    for (int k = 0; k < 16; k++) {
        int idx = k * 256 + tid;         // 0..4095
        int w  = idx >> 4;
        int f4 = idx & 15;
        float mv = sm_m[w];
        float4 sc = sm_s[f4];
        float4 o;
        o.x = mv * sc.x;
        o.y = mv * sc.y;
        o.z = mv * sc.z;
        o.w = mv * sc.w;
        __stcs(&orow[idx], o);
    }
}

extern "C" void kernel_launch(void* const* d_in, const int* in_sizes, int n_in,
                              void* d_out, int out_size) {
    const float* lfi = (const float*)d_in[0];          // [4,9,256,256,9]
    const float4* fm4 = (const float4*)d_in[1];        // [4,256,256,64] as float4
    float4* out = (float4*)d_out;                      // [4,256,256,64]

    colmean_fmaps_kernel<<<B_ * W_, 256>>>(fm4);       // B: block per (b,w)
    normalize_kernel<<<B_ * F_, 256>>>();              // C: block per (b,f)
    fused_m_out_kernel<<<B_ * H_, 256>>>(lfi, out);    // A+D fused
}